// round 2
// baseline (speedup 1.0000x reference)
#include <cuda_runtime.h>
#include <cstdint>

// ---------------- problem constants ----------------
#define IN_DIM   57
#define HDIM     128
#define NCAT     18
#define SEQT     128
#define KX       64            // x-projection K padded 57 -> 64
#define KT       32            // k-tile streamed from L2
#define NGATE    512           // 4*H
#define MROWS    32            // batch rows per CTA
#define NBLOCKS  128           // 4096 / 32
#define NTHREADS 256
#define XROW     68            // duplicated row stride in floats (2*32 + 4 pad)

#define W_STAGE  (KT * NGATE)          // 16384 floats per stage
#define W_FLOATS (2 * W_STAGE)         // 32768
#define X_FLOATS (KX * XROW)           // 4352  (single buffer, duplicated)
#define H_FLOATS (HDIM * XROW)         // 8704  (single buffer, duplicated)
#define SMEM_BYTES ((W_FLOATS + X_FLOATS + H_FLOATS) * 4 + 16)

typedef unsigned long long u64;

// fused weight matrix [k][n] (k 0..63 -> W_ih^T zero-padded, 64..191 -> W_hh^T)
__device__ __align__(128) float g_wcat[(KX + HDIM) * NGATE];
__device__ __align__(128) float g_bias[NGATE];

// ---------------- small helpers ----------------
__device__ __forceinline__ uint32_t smem_u32(const void* p) {
    return (uint32_t)__cvta_generic_to_shared(p);
}
__device__ __forceinline__ u64 pack2(float a, float b) {
    u64 d; asm("mov.b64 %0, {%1, %2};" : "=l"(d) : "f"(a), "f"(b)); return d;
}
__device__ __forceinline__ float2 unpk(u64 v) {
    float2 r; asm("mov.b64 {%0, %1}, %2;" : "=f"(r.x), "=f"(r.y) : "l"(v)); return r;
}
__device__ __forceinline__ void fma2(u64& d, u64 a, u64 b) {
    asm("fma.rn.f32x2 %0, %1, %2, %0;" : "+l"(d) : "l"(a), "l"(b));
}
__device__ __forceinline__ float ex2f(float x) {
    float y; asm("ex2.approx.f32 %0, %1;" : "=f"(y) : "f"(x)); return y;
}
__device__ __forceinline__ float rcpf(float x) {
    float y; asm("rcp.approx.f32 %0, %1;" : "=f"(y) : "f"(x)); return y;
}
__device__ __forceinline__ float sigf(float x) {
    return rcpf(1.0f + ex2f(-1.4426950408889634f * x));
}
__device__ __forceinline__ float tanhf_fast(float x) {
    float e = ex2f(2.8853900817779268f * x);     // e^{2x}
    return 1.0f - 2.0f * rcpf(e + 1.0f);
}
__device__ __forceinline__ void sts_dup(float* p, float v) {
    *(float2*)p = make_float2(v, v);             // STS.64 of (v,v)
}
__device__ __forceinline__ void mbar_wait(uint32_t mbar, int phase) {
    asm volatile(
        "{\n\t.reg .pred P;\n\t"
        "LAB_WAIT_%=:\n\t"
        "mbarrier.try_wait.parity.acquire.cta.shared::cta.b64 P, [%0], %1, 0x989680;\n\t"
        "@P bra.uni LAB_DONE_%=;\n\t"
        "bra.uni LAB_WAIT_%=;\n\t"
        "LAB_DONE_%=:\n\t}"
        :: "r"(mbar), "r"(phase) : "memory");
}
__device__ __forceinline__ void issue_tile(uint32_t dst, const float* src, uint32_t mbar) {
    const int bytes = KT * NGATE * 4;
    asm volatile("mbarrier.arrive.expect_tx.shared.b64 _, [%0], %1;"
                 :: "r"(mbar), "r"(bytes) : "memory");
    asm volatile("cp.async.bulk.shared::cluster.global.mbarrier::complete_tx::bytes "
                 "[%0], [%1], %2, [%3];"
                 :: "r"(dst), "l"(src), "r"(bytes), "r"(mbar) : "memory");
}
// load x[:, tt, :] for this CTA's 32 rows, DUPLICATED into dst[k][2m], zero-pad k>=57
__device__ __forceinline__ void load_x(const float* __restrict__ xin, int m0, int tt,
                                       float* dst, int tid) {
    int m  = tid >> 3;
    int kb = (tid & 7) * 8;
    const float* src = xin + ((size_t)(m0 + m) * SEQT + tt) * IN_DIM;
#pragma unroll
    for (int u = 0; u < 8; ++u) {
        int k = kb + u;
        float v = (k < IN_DIM) ? src[k] : 0.0f;
        *(float2*)(dst + k * XROW + 2 * m) = make_float2(v, v);
    }
}

// one k-column of the GEMM: 8 m-pairs (pre-duplicated) x 8 n (4 gates x n-pair)
__device__ __forceinline__ void gemm_kk(const float* __restrict__ arow,
                                        const float* __restrict__ wrow,
                                        u64 (&acc)[4][8]) {
    ulonglong2 q0 = *(const ulonglong2*)(arow);
    ulonglong2 q1 = *(const ulonglong2*)(arow + 4);
    ulonglong2 q2 = *(const ulonglong2*)(arow + 8);
    ulonglong2 q3 = *(const ulonglong2*)(arow + 12);
    u64 ad[8] = { q0.x, q0.y, q1.x, q1.y, q2.x, q2.y, q3.x, q3.y };
    u64 wv[4];
    wv[0] = *(const u64*)(wrow);
    wv[1] = *(const u64*)(wrow + 128);
    wv[2] = *(const u64*)(wrow + 256);
    wv[3] = *(const u64*)(wrow + 384);
#pragma unroll
    for (int gg = 0; gg < 4; ++gg)
#pragma unroll
        for (int mi = 0; mi < 8; ++mi)
            fma2(acc[gg][mi], ad[mi], wv[gg]);
}

// ---------------- prep: build fused weight + bias ----------------
__global__ void prep_kernel(const float* __restrict__ W_ih, const float* __restrict__ W_hh,
                            const float* __restrict__ b_ih, const float* __restrict__ b_hh) {
    int n = threadIdx.x;       // gate column 0..511
    int k = blockIdx.x;        // fused K row 0..191
    float v;
    if (k < KX) v = (k < IN_DIM) ? W_ih[n * IN_DIM + k] : 0.0f;
    else        v = W_hh[n * HDIM + (k - KX)];
    g_wcat[k * NGATE + n] = v;
    if (k == 0) g_bias[n] = b_ih[n] + b_hh[n];
}

// ---------------- persistent LSTM kernel ----------------
__global__ void __launch_bounds__(NTHREADS, 1)
lstm_kernel(const float* __restrict__ xin, const float* __restrict__ W_out,
            const float* __restrict__ b_out, float* __restrict__ out) {
    extern __shared__ float smem[];
    float* w_sh = smem;                       // [2][KT][512]
    float* x_sh = smem + W_FLOATS;            // [KX][XROW]  duplicated
    float* h_sh = x_sh + X_FLOATS;            // [HDIM][XROW] duplicated
    u64*   mbar = (u64*)(h_sh + H_FLOATS);    // 2 mbarriers

    const int tid = threadIdx.x;
    const int hg  = tid & 63;                 // n-pair index (n = 2hg, 2hg+1 per gate)
    const int mg  = tid >> 6;                 // m-group of 8 rows
    const int m0  = blockIdx.x * MROWS;

    const uint32_t mb0 = smem_u32(mbar);
    const uint32_t mb1 = mb0 + 8;
    const uint32_t w0a = smem_u32(w_sh);
    const uint32_t w1a = w0a + W_STAGE * 4;

    if (tid == 0) {
        asm volatile("mbarrier.init.shared.b64 [%0], 1;" :: "r"(mb0) : "memory");
        asm volatile("mbarrier.init.shared.b64 [%0], 1;" :: "r"(mb1) : "memory");
    }
    // h(0) = 0, x(0) loaded
    for (int i = tid; i < H_FLOATS; i += NTHREADS) h_sh[i] = 0.0f;
    load_x(xin, m0, 0, x_sh, tid);
    __syncthreads();

    if (tid == 0) {
        issue_tile(w0a, g_wcat,           mb0);   // tile 0 -> stage 0
        issue_tile(w1a, g_wcat + W_STAGE, mb1);   // tile 1 -> stage 1
    }

    u64 bias2[4];
#pragma unroll
    for (int gg = 0; gg < 4; ++gg)
        bias2[gg] = pack2(g_bias[gg * HDIM + hg * 2], g_bias[gg * HDIM + hg * 2 + 1]);

    float c0[8], c1[8];
#pragma unroll
    for (int i = 0; i < 8; ++i) { c0[i] = 0.0f; c1[i] = 0.0f; }

    u64 acc[4][8], accO[4][8];

    const float* xb = x_sh + mg * 16;         // 16 floats = this group's 8 dup-pairs
    const float* hb = h_sh + mg * 16;
    float* hwr = h_sh + (mg * 8) * 2;         // epilogue write base (m part)
    const float* ws0 = w_sh + hg * 2;
    const float* ws1 = w_sh + W_STAGE + hg * 2;

    int ph0 = 0, ph1 = 0;

#define EP(mi)                                                                      \
    {                                                                               \
        float2 iv = unpk(accO[0][mi]);                                              \
        float2 fv = unpk(accO[1][mi]);                                              \
        float2 gv = unpk(accO[2][mi]);                                              \
        float2 ov = unpk(accO[3][mi]);                                              \
        float i0 = sigf(iv.x), f0 = sigf(fv.x), g0 = tanhf_fast(gv.x), o0 = sigf(ov.x); \
        c0[mi] = f0 * c0[mi] + i0 * g0;                                             \
        sts_dup(hwr + (hg * 2) * XROW + 2 * (mi), o0 * tanhf_fast(c0[mi]));         \
        float i1 = sigf(iv.y), f1 = sigf(fv.y), g1 = tanhf_fast(gv.y), o1 = sigf(ov.y); \
        c1[mi] = f1 * c1[mi] + i1 * g1;                                             \
        sts_dup(hwr + (hg * 2 + 1) * XROW + 2 * (mi), o1 * tanhf_fast(c1[mi]));     \
    }

    for (int t = 0; t < SEQT; ++t) {
        // ---------- j = 0 : x-tile 0 (stage 0), fused with epilogue of step t-1 ----------
        mbar_wait(mb0, ph0); ph0 ^= 1;
#pragma unroll
        for (int gg = 0; gg < 4; ++gg)
#pragma unroll
            for (int mi = 0; mi < 8; ++mi) acc[gg][mi] = bias2[gg];

#pragma unroll
        for (int kc = 0; kc < 8; ++kc) {
            if (t > 0) EP(kc);
#pragma unroll 2
            for (int k2 = 0; k2 < 4; ++k2) {
                int kk = kc * 4 + k2;
                gemm_kk(xb + kk * XROW, ws0 + kk * NGATE, acc);
            }
        }
        __syncthreads();
        if (tid == 0) issue_tile(w0a, g_wcat + 2 * W_STAGE, mb0);   // tile 2

        // ---------- j = 1 : x-tile 1 (stage 1) ----------
        mbar_wait(mb1, ph1); ph1 ^= 1;
#pragma unroll 2
        for (int kk = 0; kk < KT; ++kk)
            gemm_kk(xb + (KT + kk) * XROW, ws1 + kk * NGATE, acc);
        __syncthreads();
        if (tid == 0) issue_tile(w1a, g_wcat + 3 * W_STAGE, mb1);   // tile 3

        // ---------- j = 2..5 : h-tiles ----------
#pragma unroll
        for (int jj = 2; jj < 6; ++jj) {
            if (jj & 1) { mbar_wait(mb1, ph1); ph1 ^= 1; }
            else        { mbar_wait(mb0, ph0); ph0 ^= 1; }
            const float* wsj = (jj & 1) ? ws1 : ws0;
            const float* ab  = hb + (jj - 2) * KT * XROW;
#pragma unroll 2
            for (int kk = 0; kk < KT; ++kk)
                gemm_kk(ab + kk * XROW, wsj + kk * NGATE, acc);
            if (jj == 2 && t + 1 < SEQT)
                load_x(xin, m0, t + 1, x_sh, tid);    // x single-buffered: j0/j1 done
            __syncthreads();
            if (t < SEQT - 1 || jj < 4) {
                int tile = (jj + 2) % 6;              // 4,5,0,1
                if (tid == 0)
                    issue_tile((jj & 1) ? w1a : w0a, g_wcat + tile * W_STAGE,
                               (jj & 1) ? mb1 : mb0);
            }
        }

        // hand gates to the deferred epilogue
#pragma unroll
        for (int gg = 0; gg < 4; ++gg)
#pragma unroll
            for (int mi = 0; mi < 8; ++mi) accO[gg][mi] = acc[gg][mi];
    }

    // ---------- final epilogue (step 127) ----------
#pragma unroll
    for (int mi = 0; mi < 8; ++mi) EP(mi);
    __syncthreads();

    // ---------- final Linear: out = h_T @ W_out^T + b_out ----------
    for (int idx = tid; idx < MROWS * NCAT; idx += NTHREADS) {
        int mm  = idx / NCAT;
        int cat = idx - mm * NCAT;
        float sacc = b_out[cat];
        const float* wr = W_out + cat * HDIM;
#pragma unroll 8
        for (int k = 0; k < HDIM; ++k)
            sacc += h_sh[k * XROW + 2 * mm] * wr[k];
        out[(size_t)(m0 + mm) * NCAT + cat] = sacc;
    }
#undef EP
}

// ---------------- launch ----------------
extern "C" void kernel_launch(void* const* d_in, const int* in_sizes, int n_in,
                              void* d_out, int out_size) {
    const float* x     = (const float*)d_in[0];
    const float* W_ih  = (const float*)d_in[1];
    const float* W_hh  = (const float*)d_in[2];
    const float* b_ih  = (const float*)d_in[3];
    const float* b_hh  = (const float*)d_in[4];
    const float* W_out = (const float*)d_in[5];
    const float* b_out = (const float*)d_in[6];
    float* out = (float*)d_out;

    cudaFuncSetAttribute(lstm_kernel, cudaFuncAttributeMaxDynamicSharedMemorySize, SMEM_BYTES);

    prep_kernel<<<KX + HDIM, NGATE>>>(W_ih, W_hh, b_ih, b_hh);
    lstm_kernel<<<NBLOCKS, NTHREADS, SMEM_BYTES>>>(x, W_out, b_out, out);
}

// round 4
// speedup vs baseline: 1.5018x; 1.5018x over previous
#include <cuda_runtime.h>
#include <cstdint>

// ---------------- problem constants ----------------
#define IN_DIM   57
#define HDIM     128
#define NCAT     18
#define SEQT     128
#define KX       64            // x-projection K padded 57 -> 64
#define KT       32            // k-tile streamed from L2
#define NGATE    512           // 4*H
#define MROWS    32            // batch rows per CTA
#define NBLOCKS  128           // 4096 / 32
#define NTHREADS 256
#define MPAD     36            // padded m-stride (144B, 16B aligned)

#define W_STAGE  (KT * NGATE)          // 16384 floats per stage
#define W_FLOATS (2 * W_STAGE)         // 32768 (two 64KB stages)
#define X_FLOATS (2 * KX * MPAD)       // 4608
#define H_FLOATS (2 * HDIM * MPAD)     // 9216
#define SMEM_BYTES ((W_FLOATS + X_FLOATS + H_FLOATS) * 4 + 32)

typedef unsigned long long u64;

// fused weight matrix [k][n] (k 0..63 -> W_ih^T zero-padded, 64..191 -> W_hh^T)
__device__ __align__(128) float g_wcat[(KX + HDIM) * NGATE];
__device__ __align__(128) float g_bias[NGATE];

// ---------------- small helpers ----------------
__device__ __forceinline__ uint32_t smem_u32(const void* p) {
    return (uint32_t)__cvta_generic_to_shared(p);
}
__device__ __forceinline__ u64 dup2(float x) {
    u64 d; asm("mov.b64 %0, {%1, %1};" : "=l"(d) : "f"(x)); return d;
}
__device__ __forceinline__ u64 pack2(float a, float b) {
    u64 d; asm("mov.b64 %0, {%1, %2};" : "=l"(d) : "f"(a), "f"(b)); return d;
}
__device__ __forceinline__ float2 unpk(u64 v) {
    float2 r; asm("mov.b64 {%0, %1}, %2;" : "=f"(r.x), "=f"(r.y) : "l"(v)); return r;
}
__device__ __forceinline__ void fma2(u64& d, u64 a, u64 b) {
    asm("fma.rn.f32x2 %0, %1, %2, %0;" : "+l"(d) : "l"(a), "l"(b));
}
__device__ __forceinline__ float ex2f(float x) {
    float y; asm("ex2.approx.f32 %0, %1;" : "=f"(y) : "f"(x)); return y;
}
__device__ __forceinline__ float rcpf(float x) {
    float y; asm("rcp.approx.f32 %0, %1;" : "=f"(y) : "f"(x)); return y;
}
__device__ __forceinline__ float sigf(float x) {
    return rcpf(1.0f + ex2f(-1.4426950408889634f * x));
}
__device__ __forceinline__ float tanhf_fast(float x) {
    float e = ex2f(2.8853900817779268f * x);     // e^{2x}
    return 1.0f - 2.0f * rcpf(e + 1.0f);
}
__device__ __forceinline__ void mbar_wait(uint32_t mbar, int phase) {
    asm volatile(
        "{\n\t.reg .pred P;\n\t"
        "LAB_WAIT_%=:\n\t"
        "mbarrier.try_wait.parity.acquire.cta.shared::cta.b64 P, [%0], %1, 0x989680;\n\t"
        "@P bra.uni LAB_DONE_%=;\n\t"
        "bra.uni LAB_WAIT_%=;\n\t"
        "LAB_DONE_%=:\n\t}"
        :: "r"(mbar), "r"(phase) : "memory");
}
__device__ __forceinline__ void bar_arrive(int id) {
    asm volatile("bar.arrive %0, %1;" :: "r"(id), "r"(NTHREADS) : "memory");
}
__device__ __forceinline__ void bar_sync_named(int id) {
    asm volatile("bar.sync %0, %1;" :: "r"(id), "r"(NTHREADS) : "memory");
}
__device__ __forceinline__ void issue_tile(uint32_t dst, const float* src, uint32_t mbar) {
    const int bytes = KT * NGATE * 4;
    asm volatile("mbarrier.arrive.expect_tx.shared.b64 _, [%0], %1;"
                 :: "r"(mbar), "r"(bytes) : "memory");
    asm volatile("cp.async.bulk.shared::cluster.global.mbarrier::complete_tx::bytes "
                 "[%0], [%1], %2, [%3];"
                 :: "r"(dst), "l"(src), "r"(bytes), "r"(mbar) : "memory");
}
// load x[:, tt, :] for this CTA's 32 rows, transposed to dst[k][m], zero-padded k>=57
__device__ __forceinline__ void load_x(const float* __restrict__ xin, int m0, int tt,
                                       float* dst, int tid) {
    int m  = tid >> 3;
    int kb = (tid & 7) * 8;
    const float* src = xin + ((size_t)(m0 + m) * SEQT + tt) * IN_DIM;
#pragma unroll
    for (int u = 0; u < 8; ++u) {
        int k = kb + u;
        dst[k * MPAD + m] = (k < IN_DIM) ? src[k] : 0.0f;
    }
}

// one full 32-k tile of the GEMM (identical body to R1's inner loop)
__device__ __forceinline__ void gemm_tile(const float* __restrict__ ab,
                                          const float* __restrict__ wb,
                                          u64 (&acc)[4][8]) {
#pragma unroll 8
    for (int kk = 0; kk < KT; ++kk) {
        float4 a0 = *(const float4*)(ab + kk * MPAD);       // broadcast within warp
        float4 a1 = *(const float4*)(ab + kk * MPAD + 4);
        u64 ad[8];
        ad[0] = dup2(a0.x); ad[1] = dup2(a0.y); ad[2] = dup2(a0.z); ad[3] = dup2(a0.w);
        ad[4] = dup2(a1.x); ad[5] = dup2(a1.y); ad[6] = dup2(a1.z); ad[7] = dup2(a1.w);
        const float* wr = wb + kk * NGATE;
        u64 wv[4];
        wv[0] = *(const u64*)(wr);
        wv[1] = *(const u64*)(wr + 128);
        wv[2] = *(const u64*)(wr + 256);
        wv[3] = *(const u64*)(wr + 384);
#pragma unroll
        for (int gg = 0; gg < 4; ++gg)
#pragma unroll
            for (int mi = 0; mi < 8; ++mi)
                fma2(acc[gg][mi], ad[mi], wv[gg]);
    }
}

// ---------------- prep: build fused weight + bias ----------------
__global__ void prep_kernel(const float* __restrict__ W_ih, const float* __restrict__ W_hh,
                            const float* __restrict__ b_ih, const float* __restrict__ b_hh) {
    int n = threadIdx.x;       // gate column 0..511
    int k = blockIdx.x;        // fused K row 0..191
    float v;
    if (k < KX) v = (k < IN_DIM) ? W_ih[n * IN_DIM + k] : 0.0f;
    else        v = W_hh[n * HDIM + (k - KX)];
    g_wcat[k * NGATE + n] = v;
    if (k == 0) g_bias[n] = b_ih[n] + b_hh[n];
}

// ---------------- persistent LSTM kernel ----------------
__global__ void __launch_bounds__(NTHREADS, 1)
lstm_kernel(const float* __restrict__ xin, const float* __restrict__ W_out,
            const float* __restrict__ b_out, float* __restrict__ out) {
    extern __shared__ float smem[];
    float* w_sh = smem;                       // [2][KT][512]
    float* x_sh = smem + W_FLOATS;            // [2][KX][MPAD]
    float* h_sh = x_sh + X_FLOATS;            // [2][HDIM][MPAD]
    u64*   mbar = (u64*)(h_sh + H_FLOATS);    // full0, full1

    const int tid = threadIdx.x;
    const int wid = tid >> 5;
    const int hg  = tid & 63;                 // n-pair index (n = 2hg, 2hg+1 per gate)
    const int mg  = tid >> 6;                 // m-group of 8 rows
    const int m0  = blockIdx.x * MROWS;

    const uint32_t mb0 = smem_u32(mbar);
    const uint32_t mb1 = mb0 + 8;
    const uint32_t w0a = smem_u32(w_sh);
    const uint32_t w1a = w0a + W_STAGE * 4;

    if (tid == 0) {
        asm volatile("mbarrier.init.shared.b64 [%0], 1;" :: "r"(mb0) : "memory");
        asm volatile("mbarrier.init.shared.b64 [%0], 1;" :: "r"(mb1) : "memory");
    }
    // h(0) = 0 (buffer 0), x(0) into buffer 0
    for (int i = tid; i < H_FLOATS; i += NTHREADS) h_sh[i] = 0.0f;
    load_x(xin, m0, 0, x_sh, tid);
    __syncthreads();

    if (tid == 0) {
        issue_tile(w0a, g_wcat,           mb0);   // tile 0 -> stage 0
        issue_tile(w1a, g_wcat + W_STAGE, mb1);   // tile 1 -> stage 1
    }

    u64 bias2[4];
#pragma unroll
    for (int gg = 0; gg < 4; ++gg)
        bias2[gg] = pack2(g_bias[gg * HDIM + hg * 2], g_bias[gg * HDIM + hg * 2 + 1]);

    float c0[8], c1[8];
#pragma unroll
    for (int i = 0; i < 8; ++i) { c0[i] = 0.0f; c1[i] = 0.0f; }

    u64 acc[4][8];

    const float* ws0 = w_sh + hg * 2;
    const float* ws1 = w_sh + W_STAGE + hg * 2;

    int ph0 = 0, ph1 = 0;     // consumer full phases

    // split-barrier stage release: warps 1-7 arrive (non-blocking); warp 0
    // syncs (blocks only warp 0) then lane 0 reissues the stage.
#define RELEASE_STAGE(barid, doissue, dsta, srcp, mbx)                \
    {                                                                 \
        if (wid == 0) {                                               \
            bar_sync_named(barid);                                    \
            if (tid == 0 && (doissue)) issue_tile(dsta, srcp, mbx);   \
        } else {                                                      \
            bar_arrive(barid);                                        \
        }                                                             \
    }

    for (int t = 0; t < SEQT; ++t) {
        const float* xb = x_sh + (t & 1) * (KX * MPAD)   + mg * 8;
        const float* hb = h_sh + (t & 1) * (HDIM * MPAD) + mg * 8;
        const bool more = (t + 1 < SEQT);

        // ---------- j = 0 : x-tile 0 (stage 0) ----------
        mbar_wait(mb0, ph0); ph0 ^= 1;
#pragma unroll
        for (int gg = 0; gg < 4; ++gg)
#pragma unroll
            for (int mi = 0; mi < 8; ++mi) acc[gg][mi] = bias2[gg];
        gemm_tile(xb, ws0, acc);
        if (more) load_x(xin, m0, t + 1, x_sh + ((t + 1) & 1) * (KX * MPAD), tid);
        RELEASE_STAGE(1, true, w0a, g_wcat + 2 * W_STAGE, mb0);     // tile 2

        // ---------- j = 1 : x-tile 1 (stage 1) ----------
        mbar_wait(mb1, ph1); ph1 ^= 1;
        gemm_tile(xb + KT * MPAD, ws1, acc);
        RELEASE_STAGE(2, true, w1a, g_wcat + 3 * W_STAGE, mb1);     // tile 3

        // ---------- j = 2 : h-tile 0 (stage 0) ----------
        mbar_wait(mb0, ph0); ph0 ^= 1;
        gemm_tile(hb, ws0, acc);
        RELEASE_STAGE(1, true, w0a, g_wcat + 4 * W_STAGE, mb0);     // tile 4

        // ---------- j = 3 : h-tile 1 (stage 1) ----------
        mbar_wait(mb1, ph1); ph1 ^= 1;
        gemm_tile(hb + KT * MPAD, ws1, acc);
        RELEASE_STAGE(2, true, w1a, g_wcat + 5 * W_STAGE, mb1);     // tile 5

        // ---------- j = 4 : h-tile 2 (stage 0) ----------
        mbar_wait(mb0, ph0); ph0 ^= 1;
        gemm_tile(hb + 2 * KT * MPAD, ws0, acc);
        RELEASE_STAGE(1, more, w0a, g_wcat, mb0);                   // tile 0 (next step)

        // ---------- j = 5 : h-tile 3 (stage 1) ----------
        mbar_wait(mb1, ph1); ph1 ^= 1;
        gemm_tile(hb + 3 * KT * MPAD, ws1, acc);
        RELEASE_STAGE(2, more, w1a, g_wcat + W_STAGE, mb1);         // tile 1 (next step)

        // ---------- epilogue: activations + c/h update ----------
        float* hout = h_sh + ((t + 1) & 1) * (HDIM * MPAD) + mg * 8;
#pragma unroll
        for (int mi = 0; mi < 8; ++mi) {
            float2 iv = unpk(acc[0][mi]);
            float2 fv = unpk(acc[1][mi]);
            float2 gv = unpk(acc[2][mi]);
            float2 ov = unpk(acc[3][mi]);
            float i0 = sigf(iv.x), f0 = sigf(fv.x), g0 = tanhf_fast(gv.x), o0 = sigf(ov.x);
            c0[mi] = f0 * c0[mi] + i0 * g0;
            hout[(hg * 2    ) * MPAD + mi] = o0 * tanhf_fast(c0[mi]);
            float i1 = sigf(iv.y), f1 = sigf(fv.y), g1 = tanhf_fast(gv.y), o1 = sigf(ov.y);
            c1[mi] = f1 * c1[mi] + i1 * g1;
            hout[(hg * 2 + 1) * MPAD + mi] = o1 * tanhf_fast(c1[mi]);
        }

        __syncthreads();   // the ONE per-step CTA barrier: h(t+1)/x(t+1) published
    }
#undef RELEASE_STAGE

    // ---------- final Linear: out = h_T @ W_out^T + b_out ----------
    const float* hfin = h_sh;   // SEQT even -> final h in buffer 0
    for (int idx = tid; idx < MROWS * NCAT; idx += NTHREADS) {
        int mm  = idx / NCAT;
        int cat = idx - mm * NCAT;
        float sacc = b_out[cat];
        const float* wr = W_out + cat * HDIM;
#pragma unroll 8
        for (int k = 0; k < HDIM; ++k)
            sacc += hfin[k * MPAD + mm] * wr[k];
        out[(size_t)(m0 + mm) * NCAT + cat] = sacc;
    }
}

// ---------------- launch ----------------
extern "C" void kernel_launch(void* const* d_in, const int* in_sizes, int n_in,
                              void* d_out, int out_size) {
    const float* x     = (const float*)d_in[0];
    const float* W_ih  = (const float*)d_in[1];
    const float* W_hh  = (const float*)d_in[2];
    const float* b_ih  = (const float*)d_in[3];
    const float* b_hh  = (const float*)d_in[4];
    const float* W_out = (const float*)d_in[5];
    const float* b_out = (const float*)d_in[6];
    float* out = (float*)d_out;

    cudaFuncSetAttribute(lstm_kernel, cudaFuncAttributeMaxDynamicSharedMemorySize, SMEM_BYTES);

    prep_kernel<<<KX + HDIM, NGATE>>>(W_ih, W_hh, b_ih, b_hh);
    lstm_kernel<<<NBLOCKS, NTHREADS, SMEM_BYTES>>>(x, W_out, b_out, out);
}